// round 11
// baseline (speedup 1.0000x reference)
#include <cuda_runtime.h>
#include <cuda_fp16.h>
#include <cstdint>
#include <cstddef>

// ---------------------------------------------------------------------------
// out[b,o] = sum_{i,l} x[b,i]*g[b,l]*pw[o,i,l] + sum_l g[b,l]*pb[o,l],
// g = softmax(x@gw+gb).  One GEMM: M=4096(b), N=1024(o), K=32832 (k=i*32+l,
// then 32 bias cols where A=g,B=pb, then 32 zero-pad cols).
//   A[b,k] = x[b,i]*g[b,l]   (fp16, generated on-chip into SMEM)
//   B[o,k] = pw[o,i,l]       (fp16 scratch, native pw memory order)
// NOTE: harness emits compute_103 PTX (no 'a' suffix) -> tcgen05 unavailable.
// Use base-target path: mma.sync.m16n8k16 (HMMA) + cp.async + ldmatrix.
// ---------------------------------------------------------------------------

#define BB     4096
#define DIN    1024
#define DOUT   1024
#define LL     32
#define KRAW   32768
#define KP     32832          // 513 * 64
#define NITER  513            // K chunks of 64

#define M_TILE 128
#define N_TILE 256
#define STAGES 3
#define A_BYTES 16384                     // 128 rows * 128 B
#define B_BYTES 32768                     // 256 rows * 128 B
#define B_OFF   (STAGES * A_BYTES)        // 49152
#define SMEM_TOTAL (B_OFF + STAGES * B_BYTES)  // 147456

// ---------------------------------------------------------------------------
// device scratch (allocation-free rule: __device__ globals)
// ---------------------------------------------------------------------------
__device__ float  d_gate[(size_t)BB * LL];      // softmax gates, f32
__device__ __half d_pwh[(size_t)DOUT * KP];     // B matrix fp16, K-major

// ---------------------------------------------------------------------------
// helpers
// ---------------------------------------------------------------------------
__device__ __forceinline__ uint32_t smem_u32(const void* p) {
    uint32_t a;
    asm("{ .reg .u64 t; cvta.to.shared.u64 t, %1; cvt.u32.u64 %0, t; }"
        : "=r"(a) : "l"(p));
    return a;
}

__device__ __forceinline__ uint32_t pack_h2(float a, float b) {
    __half2 h = __floats2half2_rn(a, b);   // a -> low 16 bits (lower address)
    return *reinterpret_cast<uint32_t*>(&h);
}

#define LDSM_X4(R0, R1, R2, R3, ADDR)                                          \
    asm volatile("ldmatrix.sync.aligned.m8n8.x4.shared.b16 {%0,%1,%2,%3}, [%4];" \
                 : "=r"(R0), "=r"(R1), "=r"(R2), "=r"(R3) : "r"(ADDR))

#define MMA16816(C, A, B0, B1)                                                 \
    asm volatile("mma.sync.aligned.m16n8k16.row.col.f32.f16.f16.f32 "          \
                 "{%0,%1,%2,%3}, {%4,%5,%6,%7}, {%8,%9}, {%0,%1,%2,%3};"       \
                 : "+f"((C)[0]), "+f"((C)[1]), "+f"((C)[2]), "+f"((C)[3])      \
                 : "r"((A)[0]), "r"((A)[1]), "r"((A)[2]), "r"((A)[3]),         \
                   "r"(B0), "r"(B1))

#define SW128(off) ((off) ^ (((off) >> 3) & 0x70))

// ---------------------------------------------------------------------------
// Kernel 1: gates = softmax(x @ gw + gb)   (one warp per row of x)
// ---------------------------------------------------------------------------
__global__ void __launch_bounds__(256)
gating_kernel(const float* __restrict__ x, const float* __restrict__ gw,
              const float* __restrict__ gb) {
    int warp = (blockIdx.x * blockDim.x + threadIdx.x) >> 5;
    int lane = threadIdx.x & 31;
    if (warp >= BB) return;
    const float* xr = x + (size_t)warp * DIN;
    float acc = 0.0f;
    for (int i0 = 0; i0 < DIN; i0 += 32) {
        float xv = xr[i0 + lane];
        #pragma unroll
        for (int j = 0; j < 32; ++j) {
            float xs = __shfl_sync(0xffffffffu, xv, j);
            acc = fmaf(xs, gw[(size_t)(i0 + j) * LL + lane], acc);
        }
    }
    acc += gb[lane];
    float m = acc;
    #pragma unroll
    for (int o = 16; o > 0; o >>= 1) m = fmaxf(m, __shfl_xor_sync(0xffffffffu, m, o));
    float e = __expf(acc - m);
    float s = e;
    #pragma unroll
    for (int o = 16; o > 0; o >>= 1) s += __shfl_xor_sync(0xffffffffu, s, o);
    d_gate[(size_t)warp * LL + lane] = e / s;
}

// ---------------------------------------------------------------------------
// Kernel 2: B build. pw f32 [o][i][l] -> fp16 d_pwh [o][k] (k = i*32+l),
// append pb as cols 32768..32799, zero-pad 32800..32831. 8 elems / thread.
// ---------------------------------------------------------------------------
__global__ void __launch_bounds__(256)
convert_kernel(const float* __restrict__ pw, const float* __restrict__ pb) {
    const size_t TOT = (size_t)DOUT * (KP / 8);
    size_t t = (size_t)blockIdx.x * 256 + threadIdx.x;
    if (t >= TOT) return;
    const int KP8 = KP / 8;
    int o  = (int)(t / KP8);
    int k0 = (int)(t - (size_t)o * KP8) * 8;
    uint32_t u[4];
    if (k0 < KRAW) {
        const float4* s = reinterpret_cast<const float4*>(pw + (size_t)o * KRAW + k0);
        float4 v0 = s[0], v1 = s[1];
        u[0] = pack_h2(v0.x, v0.y); u[1] = pack_h2(v0.z, v0.w);
        u[2] = pack_h2(v1.x, v1.y); u[3] = pack_h2(v1.z, v1.w);
    } else if (k0 < KRAW + LL) {
        const float4* s = reinterpret_cast<const float4*>(pb + (size_t)o * LL + (k0 - KRAW));
        float4 v0 = s[0], v1 = s[1];
        u[0] = pack_h2(v0.x, v0.y); u[1] = pack_h2(v0.z, v0.w);
        u[2] = pack_h2(v1.x, v1.y); u[3] = pack_h2(v1.z, v1.w);
    } else {
        u[0] = u[1] = u[2] = u[3] = 0u;
    }
    *reinterpret_cast<uint4*>(d_pwh + (size_t)o * KP + k0) =
        make_uint4(u[0], u[1], u[2], u[3]);
}

// ---------------------------------------------------------------------------
// Kernel 3: main GEMM.  512 threads, CTA tile M128 x N256, K-chunk 64,
// 3-stage cp.async pipeline, warp tile m32 x n64 (16 warps = 4m x 4n),
// grid = 32 M-tiles x 4 N-tiles = 128 CTAs (one wave).
// ---------------------------------------------------------------------------
__global__ void __launch_bounds__(512, 1)
moe_gemm_kernel(const float* __restrict__ x, float* __restrict__ out) {
    extern __shared__ char smem[];
    const uint32_t sb = smem_u32(smem);
    const int tid  = threadIdx.x;
    const int lane = tid & 31;
    const int wid  = tid >> 5;
    const int m_tile = blockIdx.x >> 2;
    const int n_tile = blockIdx.x & 3;
    const int b0 = m_tile * M_TILE;
    const int n0 = n_tile * N_TILE;

    // ---- producer setup: thread -> (row pr, quarter pq) of the A chunk ----
    const int pr    = tid >> 2;          // 0..127 : A row within tile
    const int pq    = tid & 3;           // quarter: bit1 = which i, bit0 = l half
    const int i_loc = pq >> 1;           // 0 or 1 : which of the 2 i's in chunk
    float g[16];
    {
        const float4* gp = reinterpret_cast<const float4*>(
            d_gate + (size_t)(b0 + pr) * LL + (pq & 1) * 16);
        #pragma unroll
        for (int j = 0; j < 4; ++j) {
            float4 v = gp[j];
            g[4*j+0] = v.x; g[4*j+1] = v.y; g[4*j+2] = v.z; g[4*j+3] = v.w;
        }
    }
    const float* xrow = x + (size_t)(b0 + pr) * DIN;
    float xc = xrow[i_loc];                       // prefetch for chunk 0

    const uint32_t a_off  = (uint32_t)(pr * 128 + pq * 32);
    const uint32_t a_sw0  = SW128(a_off);
    const uint32_t a_sw1  = SW128(a_off + 16);

    const int brow = tid >> 3;                    // 0..63
    const int bc16 = tid & 7;
    const char* bsrc = reinterpret_cast<const char*>(
        d_pwh + (size_t)(n0 + brow) * KP + bc16 * 8);
    const uint32_t b_off0 = (uint32_t)(brow * 128 + bc16 * 16);
    const uint32_t b_sw0  = SW128(b_off0);        // +j*8192 preserves swizzle
    const size_t BSRC_STRIDE = (size_t)64 * KP * 2;   // 64 B-rows in bytes

    // ---- consumer setup: warp (wm, wn) computes m32 x n64 ----
    const int wm = wid >> 2, wn = wid & 3;
    const int m0w = wm * 32, n0w = wn * 64;
    const int rowa      = m0w + (lane & 15);            // A ldmatrix row
    const int cola      = ((lane >> 4) & 1) * 16;       // A ldmatrix col byte
    const int rowb_base = n0w + (lane & 7) + ((lane >> 4) & 1) * 8;
    const int colb      = ((lane >> 3) & 1) * 16;

    float c[2][8][4];
    #pragma unroll
    for (int f = 0; f < 2; ++f)
        #pragma unroll
        for (int p = 0; p < 8; ++p)
            #pragma unroll
            for (int q = 0; q < 4; ++q) c[f][p][q] = 0.0f;

    // ---- stage issue: B via cp.async, A generated + STS.  Always commit. ----
    auto issue = [&](int jt) {
        if (jt < NITER) {
            const int s = jt % STAGES;
            // B: 256 rows x 128 B, 4 x 16 B per thread
            {
                const uint32_t bs = sb + B_OFF + s * B_BYTES;
                const char* src = bsrc + (size_t)jt * 128;
                #pragma unroll
                for (int j = 0; j < 4; ++j) {
                    asm volatile("cp.async.cg.shared.global [%0], [%1], 16;"
                                 :: "r"(bs + b_sw0 + j * 8192u),
                                    "l"(src + j * BSRC_STRIDE) : "memory");
                }
            }
            // A: z[pr, i_loc*32 + l] = x[pr, 2*jt + i_loc] * g[pr, l]
            {
                float xv = (jt == NITER - 1) ? (i_loc ? 0.0f : 1.0f) : xc;
                uint32_t h2[8];
                #pragma unroll
                for (int j = 0; j < 8; ++j)
                    h2[j] = pack_h2(xv * g[2*j], xv * g[2*j + 1]);
                const uint32_t as = sb + s * A_BYTES;
                asm volatile("st.shared.v4.b32 [%0], {%1,%2,%3,%4};"
                             :: "r"(as + a_sw0), "r"(h2[0]), "r"(h2[1]),
                                "r"(h2[2]), "r"(h2[3]) : "memory");
                asm volatile("st.shared.v4.b32 [%0], {%1,%2,%3,%4};"
                             :: "r"(as + a_sw1), "r"(h2[4]), "r"(h2[5]),
                                "r"(h2[6]), "r"(h2[7]) : "memory");
                if (jt + 1 < NITER - 1) xc = xrow[2 * (jt + 1) + i_loc];
            }
        }
        asm volatile("cp.async.commit_group;" ::: "memory");
    };

    issue(0);
    issue(1);

    for (int it = 0; it < NITER; ++it) {
        asm volatile("cp.async.wait_group 1;" ::: "memory");
        __syncthreads();                 // stage it ready; stage it-1 drained
        issue(it + 2);                   // refill stage (it+2)%3 == (it-1)%3

        const int s = it % STAGES;
        const uint32_t as = sb + s * A_BYTES;
        const uint32_t bs = sb + B_OFF + s * B_BYTES;
        #pragma unroll
        for (int ks = 0; ks < 4; ++ks) {
            uint32_t a0[4], a1[4];
            {
                uint32_t o0 = (uint32_t)(rowa * 128 + ks * 32 + cola);
                LDSM_X4(a0[0], a0[1], a0[2], a0[3], as + SW128(o0));
                uint32_t o1 = o0 + 16 * 128;
                LDSM_X4(a1[0], a1[1], a1[2], a1[3], as + SW128(o1));
            }
            uint32_t bf[4][4];
            #pragma unroll
            for (int p = 0; p < 4; ++p) {
                uint32_t ob = (uint32_t)((rowb_base + p * 16) * 128 + ks * 32 + colb);
                LDSM_X4(bf[p][0], bf[p][1], bf[p][2], bf[p][3], bs + SW128(ob));
            }
            #pragma unroll
            for (int p = 0; p < 4; ++p) {
                MMA16816(c[0][2*p],     a0, bf[p][0], bf[p][1]);
                MMA16816(c[0][2*p + 1], a0, bf[p][2], bf[p][3]);
                MMA16816(c[1][2*p],     a1, bf[p][0], bf[p][1]);
                MMA16816(c[1][2*p + 1], a1, bf[p][2], bf[p][3]);
            }
        }
    }

    // ---- epilogue: accumulators -> global f32 ----
    const int gid = lane >> 2, tig = lane & 3;
    #pragma unroll
    for (int f = 0; f < 2; ++f) {
        #pragma unroll
        for (int p = 0; p < 8; ++p) {
            int row = b0 + m0w + f * 16 + gid;
            int col = n0 + n0w + p * 8 + tig * 2;
            *reinterpret_cast<float2*>(out + (size_t)row * DOUT + col) =
                make_float2(c[f][p][0], c[f][p][1]);
            *reinterpret_cast<float2*>(out + (size_t)(row + 8) * DOUT + col) =
                make_float2(c[f][p][2], c[f][p][3]);
        }
    }
}

// ---------------------------------------------------------------------------
// launch
// ---------------------------------------------------------------------------
extern "C" void kernel_launch(void* const* d_in, const int* in_sizes, int n_in,
                              void* d_out, int out_size) {
    const float* x  = (const float*)d_in[0];   // [4096,1024]
    const float* gw = (const float*)d_in[1];   // [1024,32]
    const float* gb = (const float*)d_in[2];   // [32]
    const float* pw = (const float*)d_in[3];   // [1024,1024,32]
    const float* pb = (const float*)d_in[4];   // [1024,32]
    float* out = (float*)d_out;                // [4096,1024]

    cudaFuncSetAttribute(moe_gemm_kernel,
                         cudaFuncAttributeMaxDynamicSharedMemorySize, SMEM_TOTAL);

    gating_kernel<<<(BB * 32) / 256, 256>>>(x, gw, gb);
    {
        const size_t TOT = (size_t)DOUT * (KP / 8);
        convert_kernel<<<(unsigned)((TOT + 255) / 256), 256>>>(pw, pb);
    }
    moe_gemm_kernel<<<(BB / M_TILE) * (DOUT / N_TILE), 512, SMEM_TOTAL>>>(x, out);
}

// round 14
// speedup vs baseline: 1.0468x; 1.0468x over previous
#include <cuda_runtime.h>
#include <cuda_fp16.h>
#include <cstdint>
#include <cstddef>

// ---------------------------------------------------------------------------
// out[b,o] = sum_{i,l} x[b,i]*g[b,l]*pw[o,i,l] + sum_l g[b,l]*pb[o,l],
// g = softmax(x@gw+gb).  One GEMM: M=4096(b), N=1024(o), K=32832 (k=i*32+l,
// +32 bias cols (A=g, B=pb), +32 zero pad).
//   A[b,k] = x[b,i]*g[b,l]  (fp16, generated on-chip into SMEM)
//   B[o,k] = pw[o,i,l]      (fp16 scratch, native pw memory order)
// Toolchain emits compute_103 PTX (no 'a') -> tcgen05 unavailable; use
// mma.sync.m16n8k16 (HMMA) + cp.async + ldmatrix.
// R11->R12: warp tile m32n64 -> m64n64 (halves LDSM traffic), 3->4 stages,
// gating+convert fused into one overlapped kernel, gating 4-way acc chains.
// ---------------------------------------------------------------------------

#define BB     4096
#define DIN    1024
#define DOUT   1024
#define LL     32
#define KRAW   32768
#define KP     32832          // 513 * 64
#define NITER  513            // K chunks of 64

#define M_TILE 128
#define N_TILE 256
#define STAGES 4
#define A_BYTES 16384                     // 128 rows * 128 B
#define B_BYTES 32768                     // 256 rows * 128 B
#define B_OFF   (STAGES * A_BYTES)        // 65536
#define SMEM_TOTAL (B_OFF + STAGES * B_BYTES)  // 196608

#define GATE_BLOCKS 512                   // 4096 warps, one per b-row
#define CONV_BLOCKS ((DOUT * (KP / 8)) / 256)   // 16416

// ---------------------------------------------------------------------------
// device scratch (allocation-free rule: __device__ globals)
// ---------------------------------------------------------------------------
__device__ float  d_gate[(size_t)BB * LL];      // softmax gates, f32
__device__ __half d_pwh[(size_t)DOUT * KP];     // B matrix fp16, K-major

// ---------------------------------------------------------------------------
// helpers
// ---------------------------------------------------------------------------
__device__ __forceinline__ uint32_t smem_u32(const void* p) {
    uint32_t a;
    asm("{ .reg .u64 t; cvta.to.shared.u64 t, %1; cvt.u32.u64 %0, t; }"
        : "=r"(a) : "l"(p));
    return a;
}

__device__ __forceinline__ uint32_t pack_h2(float a, float b) {
    __half2 h = __floats2half2_rn(a, b);   // a -> low 16 bits (lower address)
    return *reinterpret_cast<uint32_t*>(&h);
}

#define LDSM_X4(R0, R1, R2, R3, ADDR)                                          \
    asm volatile("ldmatrix.sync.aligned.m8n8.x4.shared.b16 {%0,%1,%2,%3}, [%4];" \
                 : "=r"(R0), "=r"(R1), "=r"(R2), "=r"(R3) : "r"(ADDR))

#define MMA16816(C, A, B0, B1)                                                 \
    asm volatile("mma.sync.aligned.m16n8k16.row.col.f32.f16.f16.f32 "          \
                 "{%0,%1,%2,%3}, {%4,%5,%6,%7}, {%8,%9}, {%0,%1,%2,%3};"       \
                 : "+f"((C)[0]), "+f"((C)[1]), "+f"((C)[2]), "+f"((C)[3])      \
                 : "r"((A)[0]), "r"((A)[1]), "r"((A)[2]), "r"((A)[3]),         \
                   "r"(B0), "r"(B1))

#define SW128(off) ((off) ^ (((off) >> 3) & 0x70))

// ---------------------------------------------------------------------------
// Kernel 1 (fused): blocks [0,512): gating softmax; [512,...): pw->fp16 build.
// The two halves are independent; fusing lets the DRAM-bound convert overlap
// the issue/latency-bound gating.
// ---------------------------------------------------------------------------
__global__ void __launch_bounds__(256)
pre_kernel(const float* __restrict__ x,  const float* __restrict__ gw,
           const float* __restrict__ gb, const float* __restrict__ pw,
           const float* __restrict__ pb) {
    if (blockIdx.x < GATE_BLOCKS) {
        // ---- gating: one warp per row of x ----
        int warp = (blockIdx.x * blockDim.x + threadIdx.x) >> 5;
        int lane = threadIdx.x & 31;
        const float* xr = x + (size_t)warp * DIN;
        float acc0 = 0.f, acc1 = 0.f, acc2 = 0.f, acc3 = 0.f;  // 4 indep chains
        for (int i0 = 0; i0 < DIN; i0 += 32) {
            float xv = xr[i0 + lane];
            #pragma unroll
            for (int j = 0; j < 32; j += 4) {
                float x0 = __shfl_sync(0xffffffffu, xv, j + 0);
                float x1 = __shfl_sync(0xffffffffu, xv, j + 1);
                float x2 = __shfl_sync(0xffffffffu, xv, j + 2);
                float x3 = __shfl_sync(0xffffffffu, xv, j + 3);
                acc0 = fmaf(x0, gw[(size_t)(i0 + j + 0) * LL + lane], acc0);
                acc1 = fmaf(x1, gw[(size_t)(i0 + j + 1) * LL + lane], acc1);
                acc2 = fmaf(x2, gw[(size_t)(i0 + j + 2) * LL + lane], acc2);
                acc3 = fmaf(x3, gw[(size_t)(i0 + j + 3) * LL + lane], acc3);
            }
        }
        float acc = (acc0 + acc1) + (acc2 + acc3) + gb[lane];
        float m = acc;
        #pragma unroll
        for (int o = 16; o > 0; o >>= 1) m = fmaxf(m, __shfl_xor_sync(0xffffffffu, m, o));
        float e = __expf(acc - m);
        float s = e;
        #pragma unroll
        for (int o = 16; o > 0; o >>= 1) s += __shfl_xor_sync(0xffffffffu, s, o);
        d_gate[(size_t)warp * LL + lane] = e / s;
    } else {
        // ---- convert: pw f32 [o][i][l] -> fp16 d_pwh [o][k], + pb, + pad ----
        size_t t = (size_t)(blockIdx.x - GATE_BLOCKS) * 256 + threadIdx.x;
        const int KP8 = KP / 8;
        int o  = (int)(t / KP8);
        int k0 = (int)(t - (size_t)o * KP8) * 8;
        uint32_t u[4];
        if (k0 < KRAW) {
            const float4* s = reinterpret_cast<const float4*>(pw + (size_t)o * KRAW + k0);
            float4 v0 = s[0], v1 = s[1];
            u[0] = pack_h2(v0.x, v0.y); u[1] = pack_h2(v0.z, v0.w);
            u[2] = pack_h2(v1.x, v1.y); u[3] = pack_h2(v1.z, v1.w);
        } else if (k0 < KRAW + LL) {
            const float4* s = reinterpret_cast<const float4*>(pb + (size_t)o * LL + (k0 - KRAW));
            float4 v0 = s[0], v1 = s[1];
            u[0] = pack_h2(v0.x, v0.y); u[1] = pack_h2(v0.z, v0.w);
            u[2] = pack_h2(v1.x, v1.y); u[3] = pack_h2(v1.z, v1.w);
        } else {
            u[0] = u[1] = u[2] = u[3] = 0u;
        }
        *reinterpret_cast<uint4*>(d_pwh + (size_t)o * KP + k0) =
            make_uint4(u[0], u[1], u[2], u[3]);
    }
}

// ---------------------------------------------------------------------------
// Kernel 2: main GEMM.  256 threads = 8 warps (2m x 4n), warp tile m64 x n64,
// CTA tile M128 x N256, K-chunk 64, 4-stage cp.async pipeline,
// grid = 32 M-tiles x 4 N-tiles = 128 CTAs (one wave).
// ---------------------------------------------------------------------------
__global__ void __launch_bounds__(256, 1)
moe_gemm_kernel(const float* __restrict__ x, float* __restrict__ out) {
    extern __shared__ char smem[];
    const uint32_t sb = smem_u32(smem);
    const int tid  = threadIdx.x;
    const int lane = tid & 31;
    const int wid  = tid >> 5;
    const int m_tile = blockIdx.x >> 2;
    const int n_tile = blockIdx.x & 3;
    const int b0 = m_tile * M_TILE;
    const int n0 = n_tile * N_TILE;

    // ---- producer setup: A side.  thread -> (row pr, l-half lh).
    // Covers cols {i*32 + lh*16 + j : i in {0,1}, j in [0,16)} of each chunk.
    const int pr = tid >> 1;          // 0..127
    const int lh = tid & 1;           // which 16 gates
    float g[16];
    {
        const float4* gp = reinterpret_cast<const float4*>(
            d_gate + (size_t)(b0 + pr) * LL + lh * 16);
        #pragma unroll
        for (int j = 0; j < 4; ++j) {
            float4 v = gp[j];
            g[4*j+0] = v.x; g[4*j+1] = v.y; g[4*j+2] = v.z; g[4*j+3] = v.w;
        }
    }
    const float* xrow = x + (size_t)(b0 + pr) * DIN;
    float2 xc = *reinterpret_cast<const float2*>(xrow);   // x[0], x[1] for jt=0

    uint32_t a_sw[2][2];   // [i][which 16B of the 32B span]
    #pragma unroll
    for (int i = 0; i < 2; ++i) {
        uint32_t ob = (uint32_t)(pr * 128 + i * 64 + lh * 32);
        a_sw[i][0] = SW128(ob);
        a_sw[i][1] = SW128(ob + 16);
    }

    // ---- producer setup: B side.  8 x 16B per thread per stage.
    const int brow0 = tid >> 3;                    // 0..31, j-stride 32 rows
    const int bc16  = tid & 7;
    const char* bsrc = reinterpret_cast<const char*>(
        d_pwh + (size_t)(n0 + brow0) * KP) + bc16 * 16;
    const uint32_t b_sw0 = SW128((uint32_t)(brow0 * 128 + bc16 * 16));
    const size_t BSRC_J = (size_t)32 * KP * 2;     // 32 B-rows in bytes

    // ---- consumer setup: warp (wm, wn) computes m64 x n64 ----
    const int wm = wid >> 2, wn = wid & 3;
    uint32_t a_base[4], b_base[4];
    #pragma unroll
    for (int f = 0; f < 4; ++f)
        a_base[f] = SW128((uint32_t)((wm * 64 + f * 16 + (lane & 15)) * 128
                                     + ((lane >> 4) & 1) * 16));
    #pragma unroll
    for (int p = 0; p < 4; ++p)
        b_base[p] = SW128((uint32_t)((wn * 64 + p * 16 + (lane & 7)
                                      + ((lane >> 4) & 1) * 8) * 128
                                     + ((lane >> 3) & 1) * 16));

    float c[4][8][4];
    #pragma unroll
    for (int f = 0; f < 4; ++f)
        #pragma unroll
        for (int p = 0; p < 8; ++p)
            #pragma unroll
            for (int q = 0; q < 4; ++q) c[f][p][q] = 0.0f;

    // ---- stage issue: B via cp.async, A generated + STS.  Always commit. ----
    auto issue = [&](int jt) {
        if (jt < NITER) {
            const int s = jt & (STAGES - 1);
            {   // B: 256 rows x 128 B
                const uint32_t bs = sb + B_OFF + s * B_BYTES;
                const char* src = bsrc + (size_t)jt * 128;
                #pragma unroll
                for (int j = 0; j < 8; ++j) {
                    asm volatile("cp.async.cg.shared.global [%0], [%1], 16;"
                                 :: "r"(bs + b_sw0 + j * 4096u),
                                    "l"(src + j * BSRC_J) : "memory");
                }
            }
            {   // A: z[pr, i*32+l] = x[pr, 2*jt+i] * g[pr, l]
                const uint32_t as = sb + s * A_BYTES;
                float xv0 = (jt == NITER - 1) ? 1.0f : xc.x;   // bias cols: A=g
                float xv1 = (jt == NITER - 1) ? 0.0f : xc.y;   // pad cols: A=0
                #pragma unroll
                for (int i = 0; i < 2; ++i) {
                    float xv = i ? xv1 : xv0;
                    uint32_t h2[8];
                    #pragma unroll
                    for (int j = 0; j < 8; ++j)
                        h2[j] = pack_h2(xv * g[2*j], xv * g[2*j + 1]);
                    asm volatile("st.shared.v4.b32 [%0], {%1,%2,%3,%4};"
                                 :: "r"(as + a_sw[i][0]), "r"(h2[0]), "r"(h2[1]),
                                    "r"(h2[2]), "r"(h2[3]) : "memory");
                    asm volatile("st.shared.v4.b32 [%0], {%1,%2,%3,%4};"
                                 :: "r"(as + a_sw[i][1]), "r"(h2[4]), "r"(h2[5]),
                                    "r"(h2[6]), "r"(h2[7]) : "memory");
                }
                if (jt < NITER - 2)
                    xc = *reinterpret_cast<const float2*>(xrow + 2 * (jt + 1));
            }
        }
        asm volatile("cp.async.commit_group;" ::: "memory");
    };

    issue(0); issue(1); issue(2);

    for (int it = 0; it < NITER; ++it) {
        asm volatile("cp.async.wait_group 2;" ::: "memory");
        __syncthreads();                 // stage it ready; stage it-1 drained
        issue(it + 3);                   // refill stage (it+3)&3 == (it-1)&3

        const int s = it & (STAGES - 1);
        const uint32_t as = sb + s * A_BYTES;
        const uint32_t bs = sb + B_OFF + s * B_BYTES;
        #pragma unroll
        for (int ks = 0; ks < 4; ++ks) {
            const uint32_t kx = (uint32_t)(ks << 5);
            uint32_t a[4][4], b[4][4];
            #pragma unroll
            for (int f = 0; f < 4; ++f)
                LDSM_X4(a[f][0], a[f][1], a[f][2], a[f][3], as + (a_base[f] ^ kx));
            #pragma unroll
            for (int p = 0; p < 4; ++p)
                LDSM_X4(b[p][0], b[p][1], b[p][2], b[p][3], bs + (b_base[p] ^ kx));
            #pragma unroll
            for (int f = 0; f < 4; ++f) {
                #pragma unroll
                for (int p = 0; p < 4; ++p) {
                    MMA16816(c[f][2*p],     a[f], b[p][0], b[p][1]);
                    MMA16816(c[f][2*p + 1], a[f], b[p][2], b[p][3]);
                }
            }
        }
    }

    // ---- epilogue: accumulators -> global f32 ----
    const int gid = lane >> 2, tig = lane & 3;
    #pragma unroll
    for (int f = 0; f < 4; ++f) {
        #pragma unroll
        for (int p = 0; p < 8; ++p) {
            int row = b0 + wm * 64 + f * 16 + gid;
            int col = n0 + wn * 64 + p * 8 + tig * 2;
            *reinterpret_cast<float2*>(out + (size_t)row * DOUT + col) =
                make_float2(c[f][p][0], c[f][p][1]);
            *reinterpret_cast<float2*>(out + (size_t)(row + 8) * DOUT + col) =
                make_float2(c[f][p][2], c[f][p][3]);
        }
    }
}

// ---------------------------------------------------------------------------
// launch
// ---------------------------------------------------------------------------
extern "C" void kernel_launch(void* const* d_in, const int* in_sizes, int n_in,
                              void* d_out, int out_size) {
    const float* x  = (const float*)d_in[0];   // [4096,1024]
    const float* gw = (const float*)d_in[1];   // [1024,32]
    const float* gb = (const float*)d_in[2];   // [32]
    const float* pw = (const float*)d_in[3];   // [1024,1024,32]
    const float* pb = (const float*)d_in[4];   // [1024,32]
    float* out = (float*)d_out;                // [4096,1024]

    cudaFuncSetAttribute(moe_gemm_kernel,
                         cudaFuncAttributeMaxDynamicSharedMemorySize, SMEM_TOTAL);

    pre_kernel<<<GATE_BLOCKS + CONV_BLOCKS, 256>>>(x, gw, gb, pw, pb);
    moe_gemm_kernel<<<(BB / M_TILE) * (DOUT / N_TILE), 256, SMEM_TOTAL>>>(x, out);
}

// round 16
// speedup vs baseline: 1.0959x; 1.0469x over previous
#include <cuda_runtime.h>
#include <cuda_fp16.h>
#include <cstdint>
#include <cstddef>

// ---------------------------------------------------------------------------
// out[b,o] = sum_{i,l} x[b,i]*g[b,l]*pw[o,i,l] + sum_l g[b,l]*pb[o,l],
// g = softmax(x@gw+gb).  One GEMM: M=4096(b), N=1024(o), K=32832 (k=i*32+l,
// +32 bias cols (A=g, B=pb), +32 zero pad).
//   A[b,k] = x[b,i]*g[b,l]  (fp16, generated on-chip into SMEM)
//   B[o,k] = pw[o,i,l]      (fp16 scratch, native pw memory order)
// compute_103 PTX -> no tcgen05; mma.sync.m16n8k16 + cp.async + ldmatrix.
// R14->R15: fix gate-register load permutation (gp[j] -> g2[4j..4j+3]);
// R14 had halves 8..15 and 16..23 swapped -> rel_err 0.88.
// Architecture unchanged: CTA M128xN128, 4 warps (m64n64 each), 3 stages,
// 2 CTAs/SM so producer phases of one CTA overlap MMA phases of the other.
// ---------------------------------------------------------------------------

#define BB     4096
#define DIN    1024
#define DOUT   1024
#define LL     32
#define KRAW   32768
#define KP     32832          // 513 * 64
#define NITER  513            // K chunks of 64

#define M_TILE 128
#define N_TILE 128
#define STAGES 3
#define A_BYTES 16384                     // 128 rows * 128 B
#define B_BYTES 16384                     // 128 rows * 128 B
#define B_OFF   (STAGES * A_BYTES)        // 49152
#define SMEM_TOTAL (B_OFF + STAGES * B_BYTES)  // 98304 -> 2 CTAs/SM

#define GATE_BLOCKS 512                   // 4096 warps, one per b-row
#define CONV_BLOCKS ((DOUT * (KP / 8)) / 256)   // 16416

// ---------------------------------------------------------------------------
// device scratch (allocation-free rule: __device__ globals)
// ---------------------------------------------------------------------------
__device__ __half d_gateh[(size_t)BB * LL];     // softmax gates, fp16
__device__ __half d_pwh[(size_t)DOUT * KP];     // B matrix fp16, K-major

// ---------------------------------------------------------------------------
// helpers
// ---------------------------------------------------------------------------
__device__ __forceinline__ uint32_t smem_u32(const void* p) {
    uint32_t a;
    asm("{ .reg .u64 t; cvta.to.shared.u64 t, %1; cvt.u32.u64 %0, t; }"
        : "=r"(a) : "l"(p));
    return a;
}

__device__ __forceinline__ uint32_t pack_h2(float a, float b) {
    __half2 h = __floats2half2_rn(a, b);   // a -> low 16 bits (lower address)
    return *reinterpret_cast<uint32_t*>(&h);
}

#define LDSM_X4(R0, R1, R2, R3, ADDR)                                          \
    asm volatile("ldmatrix.sync.aligned.m8n8.x4.shared.b16 {%0,%1,%2,%3}, [%4];" \
                 : "=r"(R0), "=r"(R1), "=r"(R2), "=r"(R3) : "r"(ADDR))

#define MMA16816(C, A, B0, B1)                                                 \
    asm volatile("mma.sync.aligned.m16n8k16.row.col.f32.f16.f16.f32 "          \
                 "{%0,%1,%2,%3}, {%4,%5,%6,%7}, {%8,%9}, {%0,%1,%2,%3};"       \
                 : "+f"((C)[0]), "+f"((C)[1]), "+f"((C)[2]), "+f"((C)[3])      \
                 : "r"((A)[0]), "r"((A)[1]), "r"((A)[2]), "r"((A)[3]),         \
                   "r"(B0), "r"(B1))

// ---------------------------------------------------------------------------
// Kernel 1 (fused): blocks [0,512): gating softmax (fp16 out);
// blocks [512,...): pw f32 -> fp16 build.  Independent halves overlap.
// ---------------------------------------------------------------------------
__global__ void __launch_bounds__(256)
pre_kernel(const float* __restrict__ x,  const float* __restrict__ gw,
           const float* __restrict__ gb, const float* __restrict__ pw,
           const float* __restrict__ pb) {
    if (blockIdx.x < GATE_BLOCKS) {
        // ---- gating: one warp per row of x, 4 independent fma chains ----
        int warp = (blockIdx.x * blockDim.x + threadIdx.x) >> 5;
        int lane = threadIdx.x & 31;
        const float* xr = x + (size_t)warp * DIN;
        float acc0 = 0.f, acc1 = 0.f, acc2 = 0.f, acc3 = 0.f;
        for (int i0 = 0; i0 < DIN; i0 += 32) {
            float xv = xr[i0 + lane];
            #pragma unroll
            for (int j = 0; j < 32; j += 4) {
                float x0 = __shfl_sync(0xffffffffu, xv, j + 0);
                float x1 = __shfl_sync(0xffffffffu, xv, j + 1);
                float x2 = __shfl_sync(0xffffffffu, xv, j + 2);
                float x3 = __shfl_sync(0xffffffffu, xv, j + 3);
                acc0 = fmaf(x0, gw[(size_t)(i0 + j + 0) * LL + lane], acc0);
                acc1 = fmaf(x1, gw[(size_t)(i0 + j + 1) * LL + lane], acc1);
                acc2 = fmaf(x2, gw[(size_t)(i0 + j + 2) * LL + lane], acc2);
                acc3 = fmaf(x3, gw[(size_t)(i0 + j + 3) * LL + lane], acc3);
            }
        }
        float acc = (acc0 + acc1) + (acc2 + acc3) + gb[lane];
        float m = acc;
        #pragma unroll
        for (int o = 16; o > 0; o >>= 1) m = fmaxf(m, __shfl_xor_sync(0xffffffffu, m, o));
        float e = __expf(acc - m);
        float s = e;
        #pragma unroll
        for (int o = 16; o > 0; o >>= 1) s += __shfl_xor_sync(0xffffffffu, s, o);
        d_gateh[(size_t)warp * LL + lane] = __float2half_rn(e / s);
    } else {
        // ---- convert: pw f32 [o][i][l] -> fp16 d_pwh [o][k], + pb, + pad ----
        size_t t = (size_t)(blockIdx.x - GATE_BLOCKS) * 256 + threadIdx.x;
        const int KP8 = KP / 8;
        int o  = (int)(t / KP8);
        int k0 = (int)(t - (size_t)o * KP8) * 8;
        uint32_t u[4];
        if (k0 < KRAW) {
            const float4* s = reinterpret_cast<const float4*>(pw + (size_t)o * KRAW + k0);
            float4 v0 = s[0], v1 = s[1];
            u[0] = pack_h2(v0.x, v0.y); u[1] = pack_h2(v0.z, v0.w);
            u[2] = pack_h2(v1.x, v1.y); u[3] = pack_h2(v1.z, v1.w);
        } else if (k0 < KRAW + LL) {
            const float4* s = reinterpret_cast<const float4*>(pb + (size_t)o * LL + (k0 - KRAW));
            float4 v0 = s[0], v1 = s[1];
            u[0] = pack_h2(v0.x, v0.y); u[1] = pack_h2(v0.z, v0.w);
            u[2] = pack_h2(v1.x, v1.y); u[3] = pack_h2(v1.z, v1.w);
        } else {
            u[0] = u[1] = u[2] = u[3] = 0u;
        }
        *reinterpret_cast<uint4*>(d_pwh + (size_t)o * KP + k0) =
            make_uint4(u[0], u[1], u[2], u[3]);
    }
}

// ---------------------------------------------------------------------------
// Kernel 2: main GEMM.  128 threads = 4 warps (2m x 2n), warp tile m64 x n64,
// CTA tile M128 x N128, K-chunk 64, 3-stage cp.async pipeline, 2 CTAs/SM.
// grid = 32 M-tiles x 8 N-tiles = 256 CTAs (one wave at occ 2).
// ---------------------------------------------------------------------------
__global__ void __launch_bounds__(128, 2)
moe_gemm_kernel(const float* __restrict__ x, float* __restrict__ out) {
    extern __shared__ char smem[];
    const uint32_t sb = smem_u32(smem);
    const int tid  = threadIdx.x;
    const int lane = tid & 31;
    const int wid  = tid >> 5;
    const int m_tile = blockIdx.x >> 3;
    const int n_tile = blockIdx.x & 7;
    const int b0 = m_tile * M_TILE;
    const int n0 = n_tile * N_TILE;

    // ---- producer setup: A side.  thread -> full row r = tid (64 cols/chunk)
    const int r = tid;
    uint32_t g2[16];                       // 32 fp16 gates as 16 h2 regs
    {
        const uint4* gp = reinterpret_cast<const uint4*>(
            d_gateh + (size_t)(b0 + r) * LL);
        #pragma unroll
        for (int j = 0; j < 4; ++j) {      // FIX: gp[j] -> g2[4j .. 4j+3]
            uint4 v = gp[j];
            g2[4*j+0] = v.x; g2[4*j+1] = v.y;
            g2[4*j+2] = v.z; g2[4*j+3] = v.w;
        }
    }
    const float* xrow = x + (size_t)(b0 + r) * DIN;
    float2 xc = *reinterpret_cast<const float2*>(xrow);     // x[0],x[1] for jt=0

    // A STS base with swizzle folded to XOR form: addr(i,q) = abase ^ (i*64+q*16)
    const uint32_t abase = (uint32_t)(r * 128) ^ ((uint32_t)(r & 7) << 4);

    // ---- producer setup: B side.  8 x 16B cp.async per thread per stage.
    const int brow0 = tid >> 3;                    // 0..15, j-stride 16 rows
    const int bc16  = tid & 7;
    const char* bsrc = reinterpret_cast<const char*>(
        d_pwh + (size_t)(n0 + brow0) * KP) + bc16 * 16;
    const uint32_t bbase = (uint32_t)(brow0 * 128 + bc16 * 16)
                         ^ ((uint32_t)(brow0 & 7) << 4);
    const size_t BSRC_J = (size_t)16 * KP * 2;     // 16 B-rows in bytes

    // ---- consumer setup: warp (wm, wn) computes m64 x n64 ----
    const int wm = wid >> 1, wn = wid & 1;
    uint32_t a_base[4], b_base[4];
    #pragma unroll
    for (int f = 0; f < 4; ++f) {
        int ra = wm * 64 + f * 16 + (lane & 15);
        a_base[f] = ((uint32_t)(ra * 128) ^ ((uint32_t)(ra & 7) << 4))
                  ^ (uint32_t)(((lane >> 4) & 1) * 16);
    }
    #pragma unroll
    for (int p = 0; p < 4; ++p) {
        int rb = wn * 64 + p * 16 + (lane & 7) + ((lane >> 4) & 1) * 8;
        b_base[p] = ((uint32_t)(rb * 128) ^ ((uint32_t)(rb & 7) << 4))
                  ^ (uint32_t)(((lane >> 3) & 1) * 16);
    }

    float c[4][8][4];
    #pragma unroll
    for (int f = 0; f < 4; ++f)
        #pragma unroll
        for (int p = 0; p < 8; ++p)
            #pragma unroll
            for (int q = 0; q < 4; ++q) c[f][p][q] = 0.0f;

    // ---- stage issue: B via cp.async, A generated (HMUL2) + STS ----
    int prod_s = 0;
    auto issue = [&](int jt) {
        if (jt < NITER) {
            const uint32_t as = sb + prod_s * A_BYTES;
            const uint32_t bs = sb + B_OFF + prod_s * B_BYTES;
            {   // B: 128 rows x 128 B
                const char* src = bsrc + (size_t)jt * 128;
                #pragma unroll
                for (int j = 0; j < 8; ++j) {
                    asm volatile("cp.async.cg.shared.global [%0], [%1], 16;"
                                 :: "r"(bs + bbase + j * 2048u),
                                    "l"(src + j * BSRC_J) : "memory");
                }
            }
            {   // A: z[r, i*32+l] = x[r, 2*jt+i] * g[r, l]
                float xv0 = (jt == NITER - 1) ? 1.0f : xc.x;   // bias cols: A=g
                float xv1 = (jt == NITER - 1) ? 0.0f : xc.y;   // pad cols: A=0
                #pragma unroll
                for (int i = 0; i < 2; ++i) {
                    __half2 xh = __float2half2_rn(i ? xv1 : xv0);
                    uint32_t v[16];
                    #pragma unroll
                    for (int j = 0; j < 16; ++j) {
                        __half2 pr = __hmul2(xh, *reinterpret_cast<__half2*>(&g2[j]));
                        v[j] = *reinterpret_cast<uint32_t*>(&pr);
                    }
                    #pragma unroll
                    for (int q = 0; q < 4; ++q) {
                        asm volatile("st.shared.v4.b32 [%0], {%1,%2,%3,%4};"
                                     :: "r"(as + (abase ^ (uint32_t)(i * 64 + q * 16))),
                                        "r"(v[4*q]), "r"(v[4*q+1]),
                                        "r"(v[4*q+2]), "r"(v[4*q+3]) : "memory");
                    }
                }
                if (jt < NITER - 2)
                    xc = *reinterpret_cast<const float2*>(xrow + 2 * (jt + 1));
            }
        }
        asm volatile("cp.async.commit_group;" ::: "memory");
        if (++prod_s == STAGES) prod_s = 0;
    };

    issue(0); issue(1);

    int cons_s = 0;
    for (int it = 0; it < NITER; ++it) {
        asm volatile("cp.async.wait_group 1;" ::: "memory");
        __syncthreads();                 // stage 'it' ready; stage it-1 drained

        const uint32_t as = sb + cons_s * A_BYTES;
        const uint32_t bs = sb + B_OFF + cons_s * B_BYTES;
        if (++cons_s == STAGES) cons_s = 0;

        #pragma unroll
        for (int ks = 0; ks < 4; ++ks) {
            const uint32_t kx = (uint32_t)(ks << 5);
            uint32_t a[4][4], b[4][4];
            #pragma unroll
            for (int f = 0; f < 4; ++f)
                LDSM_X4(a[f][0], a[f][1], a[f][2], a[f][3], as + (a_base[f] ^ kx));
            #pragma unroll
            for (int p = 0; p < 4; ++p)
                LDSM_X4(b[p][0], b[p][1], b[p][2], b[p][3], bs + (b_base[p] ^ kx));
            if (ks == 0) issue(it + 2);   // hide producer under LDSM latency
            #pragma unroll
            for (int f = 0; f < 4; ++f) {
                #pragma unroll
                for (int p = 0; p < 4; ++p) {
                    MMA16816(c[f][2*p],     a[f], b[p][0], b[p][1]);
                    MMA16816(c[f][2*p + 1], a[f], b[p][2], b[p][3]);
                }
            }
        }
    }

    // ---- epilogue: accumulators -> global f32 ----
    const int gid = lane >> 2, tig = lane & 3;
    #pragma unroll
    for (int f = 0; f < 4; ++f) {
        #pragma unroll
        for (int p = 0; p < 8; ++p) {
            int row = b0 + wm * 64 + f * 16 + gid;
            int col = n0 + wn * 64 + p * 8 + tig * 2;
            *reinterpret_cast<float2*>(out + (size_t)row * DOUT + col) =
                make_float2(c[f][p][0], c[f][p][1]);
            *reinterpret_cast<float2*>(out + (size_t)(row + 8) * DOUT + col) =
                make_float2(c[f][p][2], c[f][p][3]);
        }
    }
}

// ---------------------------------------------------------------------------
// launch
// ---------------------------------------------------------------------------
extern "C" void kernel_launch(void* const* d_in, const int* in_sizes, int n_in,
                              void* d_out, int out_size) {
    const float* x  = (const float*)d_in[0];   // [4096,1024]
    const float* gw = (const float*)d_in[1];   // [1024,32]
    const float* gb = (const float*)d_in[2];   // [32]
    const float* pw = (const float*)d_in[3];   // [1024,1024,32]
    const float* pb = (const float*)d_in[4];   // [1024,32]
    float* out = (float*)d_out;                // [4096,1024]

    cudaFuncSetAttribute(moe_gemm_kernel,
                         cudaFuncAttributeMaxDynamicSharedMemorySize, SMEM_TOTAL);

    pre_kernel<<<GATE_BLOCKS + CONV_BLOCKS, 256>>>(x, gw, gb, pw, pb);
    moe_gemm_kernel<<<(BB / M_TILE) * (DOUT / N_TILE), 128, SMEM_TOTAL>>>(x, out);
}